// round 8
// baseline (speedup 1.0000x reference)
#include <cuda_runtime.h>
#include <cstdint>

// Binarize: x[4096, 8192] fp32, depth[3] -> out[4096, 3, 1024] float32,
// each output element = numeric value of the big-endian packed byte.
//
// R8: each thread owns 16 consecutive floats per iteration (4 front-batched
// LDG.128 -> MLP=4, double R7's in-flight depth), emitting 2 bytes per depth
// plane as one coalesced float2 store per plane. Pack via float accumulation
// on the fma pipe (exact: sums of distinct powers of two <= 255).
// Reads .cs (streaming), writes .cg (output stays L2-resident across graph
// replays -- the R6 win). Persistent grid.

#define COLS 8192
#define BPR  (COLS / 8)      // 1024 packed bytes (floats) per row per plane
#define F2PR (BPR / 2)       // 512 float2 slots per row per plane

__device__ __forceinline__ float pack8f(const float4 u, const float4 v, float d)
{
    // Big-endian: element e weight 2^(7-e). u = elements 0..3, v = 4..7.
    float acc = 0.0f;
    if (u.x > d) acc += 128.0f;
    if (u.y > d) acc += 64.0f;
    if (u.z > d) acc += 32.0f;
    if (u.w > d) acc += 16.0f;
    if (v.x > d) acc += 8.0f;
    if (v.y > d) acc += 4.0f;
    if (v.z > d) acc += 2.0f;
    if (v.w > d) acc += 1.0f;
    return acc;
}

__global__ __launch_bounds__(256) void binarize_kernel(
    const float* __restrict__ x,
    const float* __restrict__ depth,
    float* __restrict__ out,
    int npairs)              // total 16-element groups = n/16
{
    const float d0 = __ldg(depth + 0);
    const float d1 = __ldg(depth + 1);
    const float d2 = __ldg(depth + 2);

    const float4* __restrict__ x4 = reinterpret_cast<const float4*>(x);

    const int stride = gridDim.x * blockDim.x;
#pragma unroll 1
    for (int p = blockIdx.x * blockDim.x + threadIdx.x; p < npairs; p += stride) {
        // Front-batch 4 independent LDG.128 (16 consecutive floats).
        const float4 v0 = __ldcs(x4 + 4 * (size_t)p + 0);
        const float4 v1 = __ldcs(x4 + 4 * (size_t)p + 1);
        const float4 v2 = __ldcs(x4 + 4 * (size_t)p + 2);
        const float4 v3 = __ldcs(x4 + 4 * (size_t)p + 3);

        // Byte A = elements 0..7 (v0,v1), byte B = elements 8..15 (v2,v3).
        float2 r0, r1, r2;
        r0.x = pack8f(v0, v1, d0);  r0.y = pack8f(v2, v3, d0);
        r1.x = pack8f(v0, v1, d1);  r1.y = pack8f(v2, v3, d1);
        r2.x = pack8f(v0, v1, d2);  r2.y = pack8f(v2, v3, d2);

        // p indexes float2 slots: row = p / 512, slot-in-row = p % 512.
        const int row = p >> 9;
        const int t   = p & (F2PR - 1);
        float2* o = reinterpret_cast<float2*>(out + (size_t)row * (3 * BPR)) + t;
        __stcg(o,             r0);
        __stcg(o + F2PR,      r1);
        __stcg(o + 2 * F2PR,  r2);
    }
}

extern "C" void kernel_launch(void* const* d_in, const int* in_sizes, int n_in,
                              void* d_out, int out_size) {
    const float* x     = (const float*)d_in[0];
    const float* depth = (const float*)d_in[1];
    float*       out   = (float*)d_out;

    const int n      = in_sizes[0];    // 4096 * 8192
    const int npairs = n / 16;         // 16 elements (2 bytes/plane) per iter

    const int block = 256;
    int grid = 148 * 8;                // persistent: 8 blocks/SM
    const int max_grid = (npairs + block - 1) / block;
    if (grid > max_grid) grid = max_grid;

    binarize_kernel<<<grid, block>>>(x, depth, out, npairs);
}

// round 10
// speedup vs baseline: 1.0501x; 1.0501x over previous
#include <cuda_runtime.h>
#include <cstdint>

// Binarize: x[4096, 8192] fp32, depth[3] -> out[4096, 3, 1024] float32,
// each output element = numeric value of the big-endian packed byte.
//
// R9 (resubmit after infra failure): R7 structure (8 consecutive floats per
// thread, 32B lane stride = L1-optimal, ldcs reads, stcg writes keeping the
// output L2-resident across graph replays) + x2 grid-stride unroll where the
// second chunk is c+S with S a multiple of 1024: its row/t decompose as
// (row + S/1024, t), so both chunks share ONE index chain and the 4 LDG.128
// are front-batched (per-warp MLP=4). Pack via float accumulation on the
// fma pipe (exact for sums of distinct powers of two <= 255).

#define COLS 8192
#define BPR  (COLS / 8)     // 1024 packed bytes (output floats) per row per plane

__device__ __forceinline__ float pack8f(const float4 u, const float4 v, float d)
{
    // Big-endian: element e has weight 2^(7-e). u = elems 0..3, v = 4..7.
    float acc = 0.0f;
    if (u.x > d) acc += 128.0f;
    if (u.y > d) acc += 64.0f;
    if (u.z > d) acc += 32.0f;
    if (u.w > d) acc += 16.0f;
    if (v.x > d) acc += 8.0f;
    if (v.y > d) acc += 4.0f;
    if (v.z > d) acc += 2.0f;
    if (v.w > d) acc += 1.0f;
    return acc;
}

__global__ __launch_bounds__(256) void binarize_kernel(
    const float* __restrict__ x,
    const float* __restrict__ depth,
    float* __restrict__ out,
    int nchunks)            // total 8-element chunks = n/8
{
    const float d0 = __ldg(depth + 0);
    const float d1 = __ldg(depth + 1);
    const float d2 = __ldg(depth + 2);

    const float4* __restrict__ x4 = reinterpret_cast<const float4*>(x);

    const int S = gridDim.x * blockDim.x;        // multiple of 1024 by launcher
    const int rowoff = (S >> 10) * (3 * BPR);    // output offset of chunk c+S
    int c = blockIdx.x * blockDim.x + threadIdx.x;

#pragma unroll 1
    for (; c + S < nchunks; c += 2 * S) {
        // Front-batch 4 independent LDG.128 (chunks c and c+S).
        const float4 a0 = __ldcs(x4 + 2 * (size_t)c);
        const float4 b0 = __ldcs(x4 + 2 * (size_t)c + 1);
        const float4 a1 = __ldcs(x4 + 2 * (size_t)(c + S));
        const float4 b1 = __ldcs(x4 + 2 * (size_t)(c + S) + 1);

        const float r00 = pack8f(a0, b0, d0);
        const float r01 = pack8f(a0, b0, d1);
        const float r02 = pack8f(a0, b0, d2);
        const float r10 = pack8f(a1, b1, d0);
        const float r11 = pack8f(a1, b1, d1);
        const float r12 = pack8f(a1, b1, d2);

        // One index chain serves both chunks: (c+S) -> same t, row + S/1024.
        const int row = c >> 10;
        const int t   = c & (BPR - 1);
        float* o = out + (size_t)row * (3 * BPR) + t;
        __stcg(o,                    r00);
        __stcg(o + BPR,              r01);
        __stcg(o + 2 * BPR,          r02);
        __stcg(o + rowoff,           r10);
        __stcg(o + rowoff + BPR,     r11);
        __stcg(o + rowoff + 2 * BPR, r12);
    }
    // Epilogue: at most one unpaired chunk per thread.
    if (c < nchunks) {
        const float4 a = __ldcs(x4 + 2 * (size_t)c);
        const float4 b = __ldcs(x4 + 2 * (size_t)c + 1);
        const int row = c >> 10;
        const int t   = c & (BPR - 1);
        float* o = out + (size_t)row * (3 * BPR) + t;
        __stcg(o,           pack8f(a, b, d0));
        __stcg(o + BPR,     pack8f(a, b, d1));
        __stcg(o + 2 * BPR, pack8f(a, b, d2));
    }
}

extern "C" void kernel_launch(void* const* d_in, const int* in_sizes, int n_in,
                              void* d_out, int out_size) {
    const float* x     = (const float*)d_in[0];
    const float* depth = (const float*)d_in[1];
    float*       out   = (float*)d_out;

    const int n       = in_sizes[0];   // 4096 * 8192
    const int nchunks = n / 8;

    const int block = 256;
    int grid = 148 * 8;                // 1184; S = 1184*256 = 296*1024
    int max_grid = (nchunks + block - 1) / block;
    max_grid &= ~3;                    // keep S a multiple of 1024
    if (max_grid < 4) max_grid = 4;
    if (grid > max_grid) grid = max_grid;

    binarize_kernel<<<grid, block>>>(x, depth, out, nchunks);
}